// round 13
// baseline (speedup 1.0000x reference)
#include <cuda_runtime.h>

#define THRESH 0.3f
#define MARGIN 0.1f
#define WEIGHT 0.1f

constexpr int NBLOCKS  = 1024;   // 2^18 threads: B=2^23 -> exactly 32 rows/thread
constexpr int NTHREADS = 256;

// Scratch for deterministic fused reduction (no device allocation allowed).
__device__ float        g_psum[NBLOCKS];
__device__ unsigned int g_pcnt[NBLOCKS];
__device__ unsigned int g_ticket;   // zero-init; last block resets after use

__device__ __forceinline__ void row_accum(float4 p, float t,
                                          float& sum, unsigned int& cnt)
{
    float p4 = p.y, p5 = p.z, p6 = p.w;

    bool a = p4 > THRESH;
    bool b = p5 > THRESH;
    bool c = p6 > THRESH;
    bool m45  = a && b;
    bool m56  = b && c;
    bool m456 = m45 && c;

    // exactly as reference: relu(MARGIN - (p5*t - p4*t)) etc.
    float term45 = fmaxf(MARGIN - (p5 * t - p4 * t), 0.0f);
    float term56 = fmaxf(MARGIN - (p6 * t - p5 * t), 0.0f);
    float d45 = fabsf(p5 - p4);
    float d56 = fabsf(p6 - p5);
    float termO = fmaxf(d45 - d56 + MARGIN, 0.0f);

    sum += m45  ? term45 : 0.0f;
    sum += m56  ? term56 : 0.0f;
    sum += m456 ? termO  : 0.0f;
    cnt += (unsigned)m45 + (unsigned)m56 + (unsigned)m456;
}

__global__ __launch_bounds__(NTHREADS)
void tcl_fused(const float4* __restrict__ pred,   // (B,4) as float4 rows
               const float*  __restrict__ times,  // (B,)
               float* __restrict__ out,
               int B, int C)   // C: rows [0,C) of pred are L2-resident; C % 4S == 0
{
    // Independent accumulators: no serial FADD chain across the unroll body.
    float        sum0 = 0.0f, sum1 = 0.0f, sum2 = 0.0f, sum3 = 0.0f;
    unsigned int cnt0 = 0,    cnt1 = 0,    cnt2 = 0,    cnt3 = 0;

    const int S   = gridDim.x * blockDim.x;        // 262144
    const int idx = blockIdx.x * blockDim.x + threadIdx.x;

    int i = idx;

    // Region 1: L2-resident pred (ldcg) + L2-resident times (ldcg).
    // C is a multiple of 4*S, so every unroll body is uniformly in-region.
    for (; i + 3 * S < C; i += 4 * S) {
        float4 p0 = __ldcg(&pred[i]);
        float4 p1 = __ldcg(&pred[i + S]);
        float4 p2 = __ldcg(&pred[i + 2 * S]);
        float4 p3 = __ldcg(&pred[i + 3 * S]);
        float  t0 = __ldcg(&times[i]);
        float  t1 = __ldcg(&times[i + S]);
        float  t2 = __ldcg(&times[i + 2 * S]);
        float  t3 = __ldcg(&times[i + 3 * S]);
        row_accum(p0, t0, sum0, cnt0);
        row_accum(p1, t1, sum1, cnt1);
        row_accum(p2, t2, sum2, cnt2);
        row_accum(p3, t3, sum3, cnt3);
    }

    // Region 2: streaming pred (ldcs, evict-first: never displaces the
    // resident set) + L2-resident times (ldcg).
    for (; i + 3 * S < B; i += 4 * S) {
        float4 p0 = __ldcs(&pred[i]);
        float4 p1 = __ldcs(&pred[i + S]);
        float4 p2 = __ldcs(&pred[i + 2 * S]);
        float4 p3 = __ldcs(&pred[i + 3 * S]);
        float  t0 = __ldcg(&times[i]);
        float  t1 = __ldcg(&times[i + S]);
        float  t2 = __ldcg(&times[i + 2 * S]);
        float  t3 = __ldcg(&times[i + 3 * S]);
        row_accum(p0, t0, sum0, cnt0);
        row_accum(p1, t1, sum1, cnt1);
        row_accum(p2, t2, sum2, cnt2);
        row_accum(p3, t3, sum3, cnt3);
    }
    for (; i < B; i += S) {
        float4 p = __ldcs(&pred[i]);
        float  t = __ldcg(&times[i]);
        row_accum(p, t, sum0, cnt0);
    }

    float        sum = (sum0 + sum1) + (sum2 + sum3);
    unsigned int cnt = (cnt0 + cnt1) + (cnt2 + cnt3);

    // Block reduction
    #pragma unroll
    for (int off = 16; off > 0; off >>= 1) {
        sum += __shfl_down_sync(0xFFFFFFFFu, sum, off);
        cnt += __shfl_down_sync(0xFFFFFFFFu, cnt, off);
    }

    __shared__ float        s_sum[NTHREADS / 32];
    __shared__ unsigned int s_cnt[NTHREADS / 32];
    __shared__ bool         s_last;
    int lane = threadIdx.x & 31;
    int wid  = threadIdx.x >> 5;
    if (lane == 0) { s_sum[wid] = sum; s_cnt[wid] = cnt; }
    __syncthreads();

    if (wid == 0) {
        sum = (lane < NTHREADS / 32) ? s_sum[lane] : 0.0f;
        cnt = (lane < NTHREADS / 32) ? s_cnt[lane] : 0u;
        #pragma unroll
        for (int off = 4; off > 0; off >>= 1) {
            sum += __shfl_down_sync(0xFFFFFFFFu, sum, off);
            cnt += __shfl_down_sync(0xFFFFFFFFu, cnt, off);
        }
        if (lane == 0) {
            g_psum[blockIdx.x] = sum;
            g_pcnt[blockIdx.x] = cnt;
            __threadfence();
            unsigned int ticket = atomicAdd(&g_ticket, 1u);
            s_last = (ticket == (unsigned)gridDim.x - 1u);
        }
    }
    __syncthreads();

    // Last block reduces all partials (values deterministic regardless of order).
    if (s_last) {
        float        fsum = 0.0f;
        unsigned int fcnt = 0;
        for (int k = threadIdx.x; k < NBLOCKS; k += NTHREADS) {
            fsum += g_psum[k];
            fcnt += g_pcnt[k];
        }
        #pragma unroll
        for (int off = 16; off > 0; off >>= 1) {
            fsum += __shfl_down_sync(0xFFFFFFFFu, fsum, off);
            fcnt += __shfl_down_sync(0xFFFFFFFFu, fcnt, off);
        }
        if (lane == 0) { s_sum[wid] = fsum; s_cnt[wid] = fcnt; }
        __syncthreads();
        if (wid == 0) {
            fsum = (lane < NTHREADS / 32) ? s_sum[lane] : 0.0f;
            fcnt = (lane < NTHREADS / 32) ? s_cnt[lane] : 0u;
            #pragma unroll
            for (int off = 4; off > 0; off >>= 1) {
                fsum += __shfl_down_sync(0xFFFFFFFFu, fsum, off);
                fcnt += __shfl_down_sync(0xFFFFFFFFu, fcnt, off);
            }
            if (lane == 0) {
                float count = (float)fcnt;
                float loss  = (count > 0.0f) ? (fsum / fmaxf(count, 1.0f)) : fsum;
                out[0] = WEIGHT * loss;
                g_ticket = 0u;   // reset for next graph replay
            }
        }
    }
}

extern "C" void kernel_launch(void* const* d_in, const int* in_sizes, int n_in,
                              void* d_out, int out_size)
{
    const float4* pred  = (const float4*)d_in[0];  // (B,4) float32
    const float*  times = (const float*)d_in[1];   // (B,1) float32
    float*        out   = (float*)d_out;

    int B = in_sizes[1];   // element count of relative_times = B

    // L2 residency plan: total resident target = times (32 MiB) +
    // cached pred slice (48 MiB) = 80 MiB. Known-good point was 64 MiB
    // (25.3us); known-bad 112 MiB (29.2us). Probing the cliff from below.
    // 48 MiB pred = 3145728 rows = 3 unroll-groups of 4*S rows.
    const int S  = NBLOCKS * NTHREADS;        // 262144
    const int G  = 4 * S;                     // 1048576 rows = 16 MiB pred
    long long budget_rows = (48LL << 20) / 16;
    int C = (int)((budget_rows / G) * G);     // 3145728
    if (C > B) C = (B / G) * G;

    tcl_fused<<<NBLOCKS, NTHREADS>>>(pred, times, out, B, C);
}